// round 1
// baseline (speedup 1.0000x reference)
#include <cuda_runtime.h>
#include <math.h>

#define NN 40000
#define NE 640000
#define H  128
#define ITERS 8   // gathers per layer; total state updates per layer = ITERS+1

// ---------------- device scratch (no dynamic allocation allowed) ----------------
__device__ int   g_counts[NN];
__device__ int   g_rowptr[NN + 1];
__device__ int   g_cursor[NN];
__device__ int   g_col[NE];
__device__ float g_xp[NN * H];
__device__ float g_state[NN * H];
__device__ float g_aggr[NN * H];
__device__ float g_wt[H * H];
__device__ int   g_is64;

// ---------------- dtype detection for edge_index (int64 vs canonicalized int32) --
__global__ void detect_kernel(const int* ei) {
    if (threadIdx.x == 0 && blockIdx.x == 0) {
        // If data is int64 (little-endian, values in [0,40000)), every odd int32
        // word is a zero high-word. If int32, odd words are random node ids.
        int any = 0;
        for (int i = 0; i < 128; i++) any |= ei[2 * i + 1];
        g_is64 = (any == 0) ? 1 : 0;
    }
}

__global__ void zero_counts_kernel() {
    int i = blockIdx.x * blockDim.x + threadIdx.x;
    if (i < NN) g_counts[i] = 0;
}

__global__ void hist_kernel(const void* __restrict__ ei) {
    int e = blockIdx.x * blockDim.x + threadIdx.x;
    if (e >= NE) return;
    int d;
    if (g_is64) d = (int)((const long long*)ei)[NE + e];
    else        d = ((const int*)ei)[NE + e];
    atomicAdd(&g_counts[d], 1);
}

__global__ void scan_kernel() {
    __shared__ int sm[1024];
    const int tid   = threadIdx.x;
    const int chunk = (NN + 1023) / 1024;  // 40
    int start = tid * chunk;
    int end   = start + chunk; if (end > NN) end = NN; if (start > NN) start = NN;
    int s = 0;
    for (int i = start; i < end; i++) s += g_counts[i];
    sm[tid] = s;
    __syncthreads();
    // inclusive Hillis-Steele scan
    for (int off = 1; off < 1024; off <<= 1) {
        int v = 0;
        if (tid >= off) v = sm[tid - off];
        __syncthreads();
        sm[tid] += v;
        __syncthreads();
    }
    int base = (tid == 0) ? 0 : sm[tid - 1];
    for (int i = start; i < end; i++) {
        g_rowptr[i] = base;
        g_cursor[i] = base;
        base += g_counts[i];
    }
    if (tid == 1023) g_rowptr[NN] = base;  // == NE
}

__global__ void scatter_kernel(const void* __restrict__ ei) {
    int e = blockIdx.x * blockDim.x + threadIdx.x;
    if (e >= NE) return;
    int s, d;
    if (g_is64) {
        s = (int)((const long long*)ei)[e];
        d = (int)((const long long*)ei)[NE + e];
    } else {
        s = ((const int*)ei)[e];
        d = ((const int*)ei)[NE + e];
    }
    int p = atomicAdd(&g_cursor[d], 1);
    g_col[p] = s;
}

// ---------------- small helpers ----------------
__global__ void transpose_kernel(const float* __restrict__ w, float* __restrict__ wt) {
    int idx = blockIdx.x * blockDim.x + threadIdx.x;   // idx = k*H + j
    if (idx < H * H) {
        int k = idx / H, j = idx % H;
        wt[idx] = w[j * H + k];
    }
}

__global__ void tanh_kernel(const float4* __restrict__ in, float4* __restrict__ out, int n4) {
    int i = blockIdx.x * blockDim.x + threadIdx.x;
    if (i >= n4) return;
    float4 v = in[i];
    v.x = tanhf(v.x); v.y = tanhf(v.y); v.z = tanhf(v.z); v.w = tanhf(v.w);
    out[i] = v;
}

// ---------------- CSR gather: aggr[dst] = sum_{src in N(dst)} state[src] -------
__global__ __launch_bounds__(256) void gather_kernel(const float4* __restrict__ state,
                                                     float4* __restrict__ aggr) {
    int w    = (blockIdx.x * blockDim.x + threadIdx.x) >> 5;
    int lane = threadIdx.x & 31;
    if (w >= NN) return;
    int beg = g_rowptr[w], end = g_rowptr[w + 1];
    float4 acc = make_float4(0.f, 0.f, 0.f, 0.f);
    for (int p = beg; p < end; p++) {
        int s = g_col[p];
        float4 v = __ldg(&state[s * 32 + lane]);
        acc.x += v.x; acc.y += v.y; acc.z += v.z; acc.w += v.w;
    }
    aggr[w * 32 + lane] = acc;
}

// ---------------- fused GEMM: C = [tanh]( A @ W  [+ XP] ),  K = N_cols = 128 ----
// Block tile: 64 rows x 128 cols; thread microtile 4x8; K-chunks of 32.
template <bool ADD, bool DOTANH>
__global__ __launch_bounds__(256) void gemm_kernel(const float* __restrict__ A,
                                                   const float* __restrict__ W,
                                                   const float* __restrict__ XP,
                                                   float* __restrict__ C) {
    __shared__ float As[64][33];    // padded: bank-conflict-free column reads
    __shared__ float Ws[32][128];
    const int tx      = threadIdx.x;
    const int rowBase = blockIdx.x * 64;
    const int cg      = tx & 15;    // column group: cols [cg*8, cg*8+8)
    const int rg      = tx >> 4;    // row group:    rows [rg*4, rg*4+4)

    float acc[4][8];
#pragma unroll
    for (int i = 0; i < 4; i++)
#pragma unroll
        for (int j = 0; j < 8; j++) acc[i][j] = 0.f;

    for (int k0 = 0; k0 < H; k0 += 32) {
        // load A tile 64x32 (512 float4, 2 per thread)
#pragma unroll
        for (int t = 0; t < 2; t++) {
            int f = tx + t * 256;
            int r = f >> 3;
            int c = (f & 7) << 2;
            float4 v = *(const float4*)(A + (rowBase + r) * H + k0 + c);
            As[r][c + 0] = v.x; As[r][c + 1] = v.y; As[r][c + 2] = v.z; As[r][c + 3] = v.w;
        }
        // load W tile 32x128 (1024 float4, 4 per thread)
#pragma unroll
        for (int t = 0; t < 4; t++) {
            int f = tx + t * 256;
            int r = f >> 5;
            int c = (f & 31) << 2;
            *(float4*)(&Ws[r][c]) = *(const float4*)(W + (k0 + r) * H + c);
        }
        __syncthreads();
#pragma unroll
        for (int kk = 0; kk < 32; kk++) {
            float a[4];
#pragma unroll
            for (int i = 0; i < 4; i++) a[i] = As[rg * 4 + i][kk];
            float4 b0 = *(const float4*)(&Ws[kk][cg * 8]);
            float4 b1 = *(const float4*)(&Ws[kk][cg * 8 + 4]);
#pragma unroll
            for (int i = 0; i < 4; i++) {
                acc[i][0] += a[i] * b0.x;
                acc[i][1] += a[i] * b0.y;
                acc[i][2] += a[i] * b0.z;
                acc[i][3] += a[i] * b0.w;
                acc[i][4] += a[i] * b1.x;
                acc[i][5] += a[i] * b1.y;
                acc[i][6] += a[i] * b1.z;
                acc[i][7] += a[i] * b1.w;
            }
        }
        __syncthreads();
    }

#pragma unroll
    for (int i = 0; i < 4; i++) {
        int row = rowBase + rg * 4 + i;
        float o[8];
#pragma unroll
        for (int j = 0; j < 8; j++) o[j] = acc[i][j];
        if (ADD) {
            float4 x0 = *(const float4*)(XP + row * H + cg * 8);
            float4 x1 = *(const float4*)(XP + row * H + cg * 8 + 4);
            o[0] += x0.x; o[1] += x0.y; o[2] += x0.z; o[3] += x0.w;
            o[4] += x1.x; o[5] += x1.y; o[6] += x1.z; o[7] += x1.w;
        }
        if (DOTANH) {
#pragma unroll
            for (int j = 0; j < 8; j++) o[j] = tanhf(o[j]);
        }
        float4 s0 = make_float4(o[0], o[1], o[2], o[3]);
        float4 s1 = make_float4(o[4], o[5], o[6], o[7]);
        *(float4*)(C + row * H + cg * 8)     = s0;
        *(float4*)(C + row * H + cg * 8 + 4) = s1;
    }
}

// ---------------- launcher ----------------
extern "C" void kernel_launch(void* const* d_in, const int* in_sizes, int n_in,
                              void* d_out, int out_size) {
    const void*  ei     = d_in[0];
    const float* x      = (const float*)d_in[1];
    const float* w_in0  = (const float*)d_in[2];
    const float* w_rec0 = (const float*)d_in[3];
    const float* w_in1  = (const float*)d_in[4];
    const float* w_rec1 = (const float*)d_in[5];
    float*       out    = (float*)d_out;

    void *pxp, *pst, *pag, *pwt;
    cudaGetSymbolAddress(&pxp, g_xp);
    cudaGetSymbolAddress(&pst, g_state);
    cudaGetSymbolAddress(&pag, g_aggr);
    cudaGetSymbolAddress(&pwt, g_wt);
    float* xp    = (float*)pxp;
    float* state = (float*)pst;
    float* aggr  = (float*)pag;
    float* wt    = (float*)pwt;

    const int n4 = NN * H / 4;

    // ---- CSR build (per launch; inputs static but no caching allowed) ----
    detect_kernel<<<1, 32>>>((const int*)ei);
    zero_counts_kernel<<<(NN + 255) / 256, 256>>>();
    hist_kernel<<<(NE + 255) / 256, 256>>>(ei);
    scan_kernel<<<1, 1024>>>();
    scatter_kernel<<<(NE + 255) / 256, 256>>>(ei);

    // ---- layer 0 ----
    transpose_kernel<<<(H * H + 255) / 256, 256>>>(w_in0, wt);
    gemm_kernel<false, false><<<NN / 64, 256>>>(x, wt, nullptr, xp);      // xp0 = x @ w_in0^T
    tanh_kernel<<<(n4 + 255) / 256, 256>>>((const float4*)xp, (float4*)state, n4); // step 0: aggr=0
    for (int it = 0; it < ITERS; it++) {
        gather_kernel<<<(NN * 32 + 255) / 256, 256>>>((const float4*)state, (float4*)aggr);
        gemm_kernel<true, true><<<NN / 64, 256>>>(aggr, w_rec0, xp, state);
    }

    // ---- layer 1 ----
    transpose_kernel<<<(H * H + 255) / 256, 256>>>(w_in1, wt);
    gemm_kernel<false, false><<<NN / 64, 256>>>(state, wt, nullptr, xp);  // xp1 = h0 @ w_in1^T
    tanh_kernel<<<(n4 + 255) / 256, 256>>>((const float4*)xp, (float4*)state, n4);
    for (int it = 0; it < ITERS; it++) {
        gather_kernel<<<(NN * 32 + 255) / 256, 256>>>((const float4*)state, (float4*)aggr);
        float* dst = (it == ITERS - 1) ? out : state;
        gemm_kernel<true, true><<<NN / 64, 256>>>(aggr, w_rec1, xp, dst);
    }
}

// round 3
// speedup vs baseline: 1.9991x; 1.9991x over previous
#include <cuda_runtime.h>
#include <cuda_bf16.h>
#include <cuda_fp16.h>
#include <math.h>
#include <stdint.h>

#define NN 40000
#define NE 640000
#define H  128
#define ITERS 8

// ---------------- device scratch ----------------
__device__ int   g_counts[NN];
__device__ int   g_rowptr[NN + 1];
__device__ int   g_cursor[NN];
__device__ int   g_col[NE];
__device__ int   g_bsums[320];
__device__ int   g_boffs[320];
__device__ float g_xp[NN * H];
__device__ __half g_state16[NN * H];
__device__ float g_aggr[NN * H];
__device__ float g_h0[NN * H];
__device__ uint4 g_wbf4[4][4352];   // per slot: [hi 128x136][lo 128x136] bf16, padded rows
__device__ int   g_is64;

#define W_PAD 136                    // padded k-stride for W in bf16 elems
#define W_HALF (128 * W_PAD)         // 17408 bf16 elems per hi/lo half
#define A_PAD 40                     // padded k-stride for A chunk in bf16 elems
#define A_HALF (128 * A_PAD)         // 5120 bf16 elems
#define SMEM_W_BYTES (2 * W_HALF * 2)        // 69632
#define SMEM_A_BYTES (2 * A_HALF * 2)        // 20480
#define SMEM_GEMM (SMEM_W_BYTES + SMEM_A_BYTES)  // 90112

// ---------------- CSR build ----------------
__global__ void detect_kernel(const int* ei) {
    if (threadIdx.x == 0 && blockIdx.x == 0) {
        int any = 0;
        for (int i = 0; i < 128; i++) any |= ei[2 * i + 1];
        g_is64 = (any == 0) ? 1 : 0;
    }
}
__global__ void zero_counts_kernel() {
    int i = blockIdx.x * blockDim.x + threadIdx.x;
    if (i < NN) g_counts[i] = 0;
}
__global__ void hist_kernel(const void* __restrict__ ei) {
    int e = blockIdx.x * blockDim.x + threadIdx.x;
    if (e >= NE) return;
    int d;
    if (g_is64) d = (int)((const long long*)ei)[NE + e];
    else        d = ((const int*)ei)[NE + e];
    atomicAdd(&g_counts[d], 1);
}
__global__ void bsum_kernel() {    // 313 blocks x 128
    int i = blockIdx.x * 128 + threadIdx.x;
    int c = (i < NN) ? g_counts[i] : 0;
    for (int o = 16; o > 0; o >>= 1) c += __shfl_down_sync(~0u, c, o);
    __shared__ int ws[4];
    if ((threadIdx.x & 31) == 0) ws[threadIdx.x >> 5] = c;
    __syncthreads();
    if (threadIdx.x == 0) g_bsums[blockIdx.x] = ws[0] + ws[1] + ws[2] + ws[3];
}
__global__ void bscan_kernel() {   // 1 block x 512
    __shared__ int sm[512];
    int t = threadIdx.x;
    int v = (t < 313) ? g_bsums[t] : 0;
    sm[t] = v;
    __syncthreads();
    for (int o = 1; o < 512; o <<= 1) {
        int u = (t >= o) ? sm[t - o] : 0;
        __syncthreads();
        sm[t] += u;
        __syncthreads();
    }
    if (t < 313) g_boffs[t] = sm[t] - v;
}
__global__ void rowptr_kernel() {  // 313 blocks x 128
    int t = threadIdx.x;
    int i = blockIdx.x * 128 + t;
    int c = (i < NN) ? g_counts[i] : 0;
    int lane = t & 31, w = t >> 5;
    int v = c;
    for (int o = 1; o < 32; o <<= 1) {
        int u = __shfl_up_sync(~0u, v, o);
        if (lane >= o) v += u;
    }
    __shared__ int ws[4], wo[4];
    if (lane == 31) ws[w] = v;
    __syncthreads();
    if (t == 0) { int s = 0; for (int j = 0; j < 4; j++) { wo[j] = s; s += ws[j]; } }
    __syncthreads();
    int excl = v - c + wo[w] + g_boffs[blockIdx.x];
    if (i < NN) { g_rowptr[i] = excl; g_cursor[i] = excl; }
    if (blockIdx.x == 0 && t == 0) g_rowptr[NN] = NE;
}
__global__ void scatter_kernel(const void* __restrict__ ei) {
    int e = blockIdx.x * blockDim.x + threadIdx.x;
    if (e >= NE) return;
    int s, d;
    if (g_is64) {
        s = (int)((const long long*)ei)[e];
        d = (int)((const long long*)ei)[NE + e];
    } else {
        s = ((const int*)ei)[e];
        d = ((const int*)ei)[NE + e];
    }
    int p = atomicAdd(&g_cursor[d], 1);
    g_col[p] = s;
}

// ---------------- weight prep: fp32 -> bf16 hi/lo into padded [n][k] layout --------
__global__ void prep_w(const float* __restrict__ w, int trans, __nv_bfloat16* __restrict__ dst) {
    int idx = blockIdx.x * blockDim.x + threadIdx.x;
    if (idx >= H * H) return;
    int n = idx >> 7, k = idx & 127;
    float a = trans ? w[k * H + n] : w[n * H + k];
    __nv_bfloat16 hi = __float2bfloat16_rn(a);
    __nv_bfloat16 lo = __float2bfloat16_rn(a - __bfloat162float(hi));
    dst[n * W_PAD + k] = hi;
    dst[W_HALF + n * W_PAD + k] = lo;
}

// ---------------- elementwise: state16 = tanh(xp) ----------------
__global__ void tanh16_kernel(const float4* __restrict__ xp, uint2* __restrict__ st, int n4) {
    int i = blockIdx.x * blockDim.x + threadIdx.x;
    if (i >= n4) return;
    float4 v = xp[i];
    __half2 a = __floats2half2_rn(tanhf(v.x), tanhf(v.y));
    __half2 b = __floats2half2_rn(tanhf(v.z), tanhf(v.w));
    uint2 o;
    o.x = *(uint32_t*)&a;
    o.y = *(uint32_t*)&b;
    st[i] = o;
}

// ---------------- CSR gather over fp16 state -> fp32 aggr ----------------
__global__ __launch_bounds__(256) void gather16_kernel(const uint2* __restrict__ st,
                                                       float4* __restrict__ ag) {
    int w    = (blockIdx.x * blockDim.x + threadIdx.x) >> 5;
    int lane = threadIdx.x & 31;
    if (w >= NN) return;
    int beg = g_rowptr[w], end = g_rowptr[w + 1];
    float4 acc = make_float4(0.f, 0.f, 0.f, 0.f);
    int p = beg;
    for (; p + 1 < end; p += 2) {
        int s0 = g_col[p], s1 = g_col[p + 1];
        uint2 v0 = __ldg(&st[(size_t)s0 * 32 + lane]);
        uint2 v1 = __ldg(&st[(size_t)s1 * 32 + lane]);
        float2 a0 = __half22float2(*(const __half2*)&v0.x);
        float2 b0 = __half22float2(*(const __half2*)&v0.y);
        float2 a1 = __half22float2(*(const __half2*)&v1.x);
        float2 b1 = __half22float2(*(const __half2*)&v1.y);
        acc.x += a0.x + a1.x; acc.y += a0.y + a1.y;
        acc.z += b0.x + b1.x; acc.w += b0.y + b1.y;
    }
    if (p < end) {
        int s0 = g_col[p];
        uint2 v0 = __ldg(&st[(size_t)s0 * 32 + lane]);
        float2 a0 = __half22float2(*(const __half2*)&v0.x);
        float2 b0 = __half22float2(*(const __half2*)&v0.y);
        acc.x += a0.x; acc.y += a0.y; acc.z += b0.x; acc.w += b0.y;
    }
    ag[(size_t)w * 32 + lane] = acc;
}

// ---------------- mma.sync helpers ----------------
__device__ __forceinline__ void mma16816(float* c, const uint32_t* a, const uint32_t* b) {
    asm volatile(
        "mma.sync.aligned.m16n8k16.row.col.f32.bf16.bf16.f32 "
        "{%0,%1,%2,%3}, {%4,%5,%6,%7}, {%8,%9}, {%0,%1,%2,%3};"
        : "+f"(c[0]), "+f"(c[1]), "+f"(c[2]), "+f"(c[3])
        : "r"(a[0]), "r"(a[1]), "r"(a[2]), "r"(a[3]), "r"(b[0]), "r"(b[1]));
}

// ---------------- tensor-core GEMM: C[m][n] = [tanh]( A @ B^T [+ XP] ) -------------
// A fp32 [NN][128], B = prepped bf16 hi/lo [n][k] padded. 3-term bf16 split.
// Block: 256 threads (8 warps), tile 128 rows x 128 cols, K chunked by 32.
template <bool ADD, bool DOTANH, bool OUTF16>
__global__ __launch_bounds__(256, 2)
void gemm_mma(const float* __restrict__ A, const uint4* __restrict__ Wslot,
              const float* __restrict__ XP, void* __restrict__ outp) {
    extern __shared__ char smem[];
    __nv_bfloat16* Ws = (__nv_bfloat16*)smem;                       // [hi|lo][128][136]
    __nv_bfloat16* As = (__nv_bfloat16*)(smem + SMEM_W_BYTES);      // [hi|lo][128][40]
    const int tid = threadIdx.x;
    const int wid = tid >> 5, lane = tid & 31;
    const int rowBase = blockIdx.x * 128;
    const int warpRow = wid * 16;

    // ---- copy W (pre-split, padded) into smem: 4352 uint4 ----
    {
        uint4* d = (uint4*)smem;
#pragma unroll
        for (int i = 0; i < 17; i++) d[tid + i * 256] = Wslot[tid + i * 256];
    }

    float acc[16][4];
#pragma unroll
    for (int nt = 0; nt < 16; nt++)
#pragma unroll
        for (int q = 0; q < 4; q++) acc[nt][q] = 0.f;

    const int qg = lane & 3;        // k sub-offset group
    const int rg = lane >> 2;       // row/col group

    for (int ch = 0; ch < 4; ch++) {
        __syncthreads();   // protect As from previous iteration readers
        // ---- load A chunk 128x32 fp32 -> bf16 hi/lo -> padded smem ----
#pragma unroll
        for (int i = 0; i < 4; i++) {
            int f = tid + i * 256;          // 0..1023 float4s
            int r = f >> 3;                 // row
            int cq = f & 7;                 // quad within 32-col chunk
            float4 a;
            int grow = rowBase + r;
            if (grow < NN) a = *(const float4*)(A + (size_t)grow * H + ch * 32 + cq * 4);
            else           a = make_float4(0.f, 0.f, 0.f, 0.f);
            __nv_bfloat16 hx = __float2bfloat16_rn(a.x);
            __nv_bfloat16 hy = __float2bfloat16_rn(a.y);
            __nv_bfloat16 hz = __float2bfloat16_rn(a.z);
            __nv_bfloat16 hw = __float2bfloat16_rn(a.w);
            __nv_bfloat16 lx = __float2bfloat16_rn(a.x - __bfloat162float(hx));
            __nv_bfloat16 ly = __float2bfloat16_rn(a.y - __bfloat162float(hy));
            __nv_bfloat16 lz = __float2bfloat16_rn(a.z - __bfloat162float(hz));
            __nv_bfloat16 lw = __float2bfloat16_rn(a.w - __bfloat162float(hw));
            __nv_bfloat162 h01(hx, hy), h23(hz, hw), l01(lx, ly), l23(lz, lw);
            uint2 hv = make_uint2(*(uint32_t*)&h01, *(uint32_t*)&h23);
            uint2 lv = make_uint2(*(uint32_t*)&l01, *(uint32_t*)&l23);
            int off = r * A_PAD + cq * 4;
            *(uint2*)(As + off) = hv;
            *(uint2*)(As + A_HALF + off) = lv;
        }
        __syncthreads();

        // ---- compute: 2 k-steps of 16 ----
#pragma unroll
        for (int ks = 0; ks < 2; ks++) {
            const int kk = ks * 16 + qg * 2;            // within-chunk k for A frags
            const int kw = ch * 32 + ks * 16 + qg * 2;  // global k for B frags
            uint32_t ah[4], al[4];
            const int r0 = warpRow + rg;
            ah[0] = *(const uint32_t*)(As + r0 * A_PAD + kk);
            ah[1] = *(const uint32_t*)(As + (r0 + 8) * A_PAD + kk);
            ah[2] = *(const uint32_t*)(As + r0 * A_PAD + kk + 8);
            ah[3] = *(const uint32_t*)(As + (r0 + 8) * A_PAD + kk + 8);
            al[0] = *(const uint32_t*)(As + A_HALF + r0 * A_PAD + kk);
            al[1] = *(const uint32_t*)(As + A_HALF + (r0 + 8) * A_PAD + kk);
            al[2] = *(const uint32_t*)(As + A_HALF + r0 * A_PAD + kk + 8);
            al[3] = *(const uint32_t*)(As + A_HALF + (r0 + 8) * A_PAD + kk + 8);
#pragma unroll
            for (int nt = 0; nt < 16; nt++) {
                const int n = nt * 8 + rg;
                uint32_t bh[2], bl[2];
                bh[0] = *(const uint32_t*)(Ws + n * W_PAD + kw);
                bh[1] = *(const uint32_t*)(Ws + n * W_PAD + kw + 8);
                bl[0] = *(const uint32_t*)(Ws + W_HALF + n * W_PAD + kw);
                bl[1] = *(const uint32_t*)(Ws + W_HALF + n * W_PAD + kw + 8);
                mma16816(acc[nt], ah, bh);
                mma16816(acc[nt], ah, bl);
                mma16816(acc[nt], al, bh);
            }
        }
    }

    // ---- epilogue ----
    const int row0 = rowBase + warpRow + rg;
#pragma unroll
    for (int half = 0; half < 2; half++) {
        const int row = row0 + half * 8;
        if (row >= NN) continue;
#pragma unroll
        for (int nt = 0; nt < 16; nt++) {
            const int col = nt * 8 + qg * 2;
            float2 o = make_float2(acc[nt][half * 2], acc[nt][half * 2 + 1]);
            if (ADD) {
                float2 xv = *(const float2*)(XP + (size_t)row * H + col);
                o.x += xv.x; o.y += xv.y;
            }
            if (DOTANH) { o.x = tanhf(o.x); o.y = tanhf(o.y); }
            if (OUTF16) {
                __half2 p = __floats2half2_rn(o.x, o.y);
                *(__half2*)((__half*)outp + (size_t)row * H + col) = p;
            } else {
                *(float2*)((float*)outp + (size_t)row * H + col) = o;
            }
        }
    }
}

// ---------------- launcher ----------------
extern "C" void kernel_launch(void* const* d_in, const int* in_sizes, int n_in,
                              void* d_out, int out_size) {
    const void*  ei     = d_in[0];
    const float* x      = (const float*)d_in[1];
    const float* w_in0  = (const float*)d_in[2];
    const float* w_rec0 = (const float*)d_in[3];
    const float* w_in1  = (const float*)d_in[4];
    const float* w_rec1 = (const float*)d_in[5];
    float*       out    = (float*)d_out;

    void *pxp, *pst, *pag, *ph0, *pwb;
    cudaGetSymbolAddress(&pxp, g_xp);
    cudaGetSymbolAddress(&pst, g_state16);
    cudaGetSymbolAddress(&pag, g_aggr);
    cudaGetSymbolAddress(&ph0, g_h0);
    cudaGetSymbolAddress(&pwb, g_wbf4);
    float*  xp    = (float*)pxp;
    __half* st    = (__half*)pst;
    float*  aggr  = (float*)pag;
    float*  h0    = (float*)ph0;
    uint4*  wbf   = (uint4*)pwb;

    cudaFuncSetAttribute(gemm_mma<false, false, false>, cudaFuncAttributeMaxDynamicSharedMemorySize, SMEM_GEMM);
    cudaFuncSetAttribute(gemm_mma<true,  true,  true>,  cudaFuncAttributeMaxDynamicSharedMemorySize, SMEM_GEMM);
    cudaFuncSetAttribute(gemm_mma<true,  true,  false>, cudaFuncAttributeMaxDynamicSharedMemorySize, SMEM_GEMM);

    const int n4 = NN * H / 4;
    const int GB = (NN + 127) / 128;   // 313

    // ---- CSR build ----
    detect_kernel<<<1, 32>>>((const int*)ei);
    zero_counts_kernel<<<(NN + 255) / 256, 256>>>();
    hist_kernel<<<(NE + 255) / 256, 256>>>(ei);
    bsum_kernel<<<GB, 128>>>();
    bscan_kernel<<<1, 512>>>();
    rowptr_kernel<<<GB, 128>>>();
    scatter_kernel<<<(NE + 255) / 256, 256>>>(ei);

    // ---- weight prep ----
    prep_w<<<64, 256>>>(w_in0,  0, (__nv_bfloat16*)(wbf + 0 * 4352));
    prep_w<<<64, 256>>>(w_rec0, 1, (__nv_bfloat16*)(wbf + 1 * 4352));
    prep_w<<<64, 256>>>(w_in1,  0, (__nv_bfloat16*)(wbf + 2 * 4352));
    prep_w<<<64, 256>>>(w_rec1, 1, (__nv_bfloat16*)(wbf + 3 * 4352));

    // ---- layer 0 ----
    gemm_mma<false, false, false><<<GB, 256, SMEM_GEMM>>>(x, wbf + 0 * 4352, nullptr, xp);
    tanh16_kernel<<<(n4 + 255) / 256, 256>>>((const float4*)xp, (uint2*)st, n4);
    for (int it = 0; it < ITERS; it++) {
        gather16_kernel<<<(NN * 32 + 255) / 256, 256>>>((const uint2*)st, (float4*)aggr);
        if (it < ITERS - 1)
            gemm_mma<true, true, true><<<GB, 256, SMEM_GEMM>>>(aggr, wbf + 1 * 4352, xp, st);
        else
            gemm_mma<true, true, false><<<GB, 256, SMEM_GEMM>>>(aggr, wbf + 1 * 4352, xp, h0);
    }

    // ---- layer 1 ----
    gemm_mma<false, false, false><<<GB, 256, SMEM_GEMM>>>(h0, wbf + 2 * 4352, nullptr, xp);
    tanh16_kernel<<<(n4 + 255) / 256, 256>>>((const float4*)xp, (uint2*)st, n4);
    for (int it = 0; it < ITERS; it++) {
        gather16_kernel<<<(NN * 32 + 255) / 256, 256>>>((const uint2*)st, (float4*)aggr);
        if (it < ITERS - 1)
            gemm_mma<true, true, true><<<GB, 256, SMEM_GEMM>>>(aggr, wbf + 3 * 4352, xp, st);
        else
            gemm_mma<true, true, false><<<GB, 256, SMEM_GEMM>>>(aggr, wbf + 3 * 4352, xp, out);
    }
}